// round 1
// baseline (speedup 1.0000x reference)
#include <cuda_runtime.h>
#include <math.h>
#include <stdint.h>

// Problem constants
#define TSEQ    2048
#define BATCH   2
#define DMODEL  1024
#define NHEAD   16
#define HEADDIM 64
#define FFDIM   4096
#define NLAYER  4
#define ROWS    (BATCH * TSEQ)          // 4096
#define QKVDIM  (3 * DMODEL)            // 3072

// -------------------- scratch (allocation-free) --------------------
__device__ float g_x  [ROWS * DMODEL];   // residual stream
__device__ float g_xn [ROWS * DMODEL];   // layernorm output
__device__ float g_qkv[ROWS * QKVDIM];   // qkv projection
__device__ float g_att[ROWS * DMODEL];   // attention output
__device__ float g_h  [ROWS * FFDIM];    // ffn hidden

// -------------------- copy --------------------
__global__ void copy_kernel(const float4* __restrict__ in, float4* __restrict__ out, int n4) {
    int i = blockIdx.x * blockDim.x + threadIdx.x;
    if (i < n4) out[i] = in[i];
}

// -------------------- layernorm --------------------
// one block per row, 256 threads, D=1024 (4 floats / thread)
__global__ void __launch_bounds__(256) ln_kernel(
    const float* __restrict__ in, const float* __restrict__ w,
    const float* __restrict__ b, float* __restrict__ out)
{
    int row = blockIdx.x;
    int tid = threadIdx.x;
    const float4* ip = (const float4*)(in + (size_t)row * DMODEL);
    float4 v = ip[tid];
    float s  = v.x + v.y + v.z + v.w;
    float sq = v.x * v.x + v.y * v.y + v.z * v.z + v.w * v.w;

    // warp reduce
    #pragma unroll
    for (int o = 16; o > 0; o >>= 1) {
        s  += __shfl_xor_sync(0xffffffffu, s,  o);
        sq += __shfl_xor_sync(0xffffffffu, sq, o);
    }
    __shared__ float reds[8], redq[8];
    int lane = tid & 31, wid = tid >> 5;
    if (lane == 0) { reds[wid] = s; redq[wid] = sq; }
    __syncthreads();
    float ts = 0.f, tq = 0.f;
    #pragma unroll
    for (int i = 0; i < 8; i++) { ts += reds[i]; tq += redq[i]; }
    float mean = ts * (1.0f / DMODEL);
    float var  = tq * (1.0f / DMODEL) - mean * mean;
    float rstd = rsqrtf(var + 1e-5f);

    float4 wv = ((const float4*)w)[tid];
    float4 bv = ((const float4*)b)[tid];
    float4 r;
    r.x = (v.x - mean) * rstd * wv.x + bv.x;
    r.y = (v.y - mean) * rstd * wv.y + bv.y;
    r.z = (v.z - mean) * rstd * wv.z + bv.z;
    r.w = (v.w - mean) * rstd * wv.w + bv.w;
    ((float4*)(out + (size_t)row * DMODEL))[tid] = r;
}

// -------------------- GEMM: C[M,N] = A[M,K] @ W[N,K]^T + bias, epilogue --------------------
// EPI: 0 = bias, 1 = bias + exact GELU, 2 = bias + residual add
// BM=BN=128, BK=16, 256 threads, 8x8 microtile per thread.
// Requires M%128==0, N%128==0, K%16==0 (all shapes here satisfy this).
template <int EPI>
__global__ void __launch_bounds__(256) gemm_kernel(
    const float* __restrict__ A, const float* __restrict__ W,
    const float* __restrict__ bias, const float* __restrict__ res,
    float* __restrict__ C, int M, int N, int K)
{
    __shared__ float As[16][132];
    __shared__ float Ws[16][132];

    int tid = threadIdx.x;
    int tx = tid & 15;          // 0..15  (N direction)
    int ty = tid >> 4;          // 0..15  (M direction)
    int m0 = blockIdx.y * 128;
    int n0 = blockIdx.x * 128;

    float acc[8][8];
    #pragma unroll
    for (int i = 0; i < 8; i++)
        #pragma unroll
        for (int j = 0; j < 8; j++) acc[i][j] = 0.f;

    for (int k0 = 0; k0 < K; k0 += 16) {
        // load 128x16 tiles of A and W (transposed into smem), float4 along K
        #pragma unroll
        for (int i = 0; i < 2; i++) {
            int f   = tid + i * 256;      // 0..511 float4 index
            int row = f >> 2;             // 0..127
            int kq  = (f & 3) * 4;        // 0,4,8,12
            float4 a4 = *(const float4*)(A + (size_t)(m0 + row) * K + k0 + kq);
            As[kq + 0][row] = a4.x; As[kq + 1][row] = a4.y;
            As[kq + 2][row] = a4.z; As[kq + 3][row] = a4.w;
            float4 w4 = *(const float4*)(W + (size_t)(n0 + row) * K + k0 + kq);
            Ws[kq + 0][row] = w4.x; Ws[kq + 1][row] = w4.y;
            Ws[kq + 2][row] = w4.z; Ws[kq + 3][row] = w4.w;
        }
        __syncthreads();
        #pragma unroll
        for (int kk = 0; kk < 16; kk++) {
            float a[8], bb[8];
            #pragma unroll
            for (int i = 0; i < 8; i++) a[i]  = As[kk][ty * 8 + i];
            #pragma unroll
            for (int j = 0; j < 8; j++) bb[j] = Ws[kk][tx * 8 + j];
            #pragma unroll
            for (int i = 0; i < 8; i++)
                #pragma unroll
                for (int j = 0; j < 8; j++) acc[i][j] += a[i] * bb[j];
        }
        __syncthreads();
    }

    // epilogue
    #pragma unroll
    for (int i = 0; i < 8; i++) {
        int row = m0 + ty * 8 + i;
        #pragma unroll
        for (int j = 0; j < 8; j++) {
            int col = n0 + tx * 8 + j;
            float v = acc[i][j] + bias[col];
            if (EPI == 1) {
                v = 0.5f * v * (1.0f + erff(v * 0.70710678118654752f));
            } else if (EPI == 2) {
                v += res[(size_t)row * N + col];
            }
            C[(size_t)row * N + col] = v;
        }
    }
}

// -------------------- flash attention (fp32, causal + ALiBi) --------------------
// grid: (T/128, H, B), block: 128 threads, 1 query per thread.
// qkv layout: row r=(b*T+t), cols [0,1024)=Q, [1024,2048)=K, [2048,3072)=V; head h at h*64.
__global__ void __launch_bounds__(128) attn_kernel(
    const float* __restrict__ qkv, float* __restrict__ out)
{
    int b    = blockIdx.z;
    int h    = blockIdx.y;
    int qblk = blockIdx.x;
    int qi   = qblk * 128 + threadIdx.x;

    __shared__ float Ks[32][64];
    __shared__ float Vs[32][64];

    // load query into registers
    float q[64];
    {
        const float4* qp = (const float4*)(qkv + ((size_t)(b * TSEQ + qi)) * QKVDIM + h * HEADDIM);
        #pragma unroll
        for (int i = 0; i < 16; i++) {
            float4 t4 = qp[i];
            q[4*i+0] = t4.x; q[4*i+1] = t4.y; q[4*i+2] = t4.z; q[4*i+3] = t4.w;
        }
    }

    float o[64];
    #pragma unroll
    for (int d = 0; d < 64; d++) o[d] = 0.f;
    float m = -INFINITY, l = 0.f;
    float slope = exp2f(-0.5f * (float)(h + 1));   // ALiBi slope for H=16

    int ntiles = qblk * 4 + 4;   // key tiles of 32, covering up to the block's max query

    for (int t = 0; t < ntiles; t++) {
        int kbase = t * 32;
        __syncthreads();   // protect previous tile reads
        // cooperative load of K,V tiles (32x64 each)
        #pragma unroll
        for (int i = 0; i < 4; i++) {
            int f = threadIdx.x + i * 128;   // 0..511 float4 index
            int r = f >> 4;                  // 0..31
            int c = (f & 15) * 4;            // 0..60
            const float* kp = qkv + ((size_t)(b * TSEQ + kbase + r)) * QKVDIM + DMODEL + h * HEADDIM + c;
            *(float4*)&Ks[r][c] = *(const float4*)kp;
            *(float4*)&Vs[r][c] = *(const float4*)(kp + DMODEL);
        }
        __syncthreads();

        // scores
        float s[32];
        #pragma unroll
        for (int j = 0; j < 32; j++) {
            float acc = 0.f;
            #pragma unroll
            for (int d4 = 0; d4 < 16; d4++) {
                float4 kv = *(const float4*)&Ks[j][d4 * 4];
                acc += q[4*d4+0] * kv.x + q[4*d4+1] * kv.y
                     + q[4*d4+2] * kv.z + q[4*d4+3] * kv.w;
            }
            int kpos = kbase + j;
            s[j] = (kpos <= qi) ? (0.125f * acc + slope * (float)(kpos - qi)) : -INFINITY;
        }

        // online softmax
        float tm = m;
        #pragma unroll
        for (int j = 0; j < 32; j++) tm = fmaxf(tm, s[j]);
        float corr = __expf(m - tm);   // 0 on first tile (m=-inf, tm finite)
        m = tm;
        l *= corr;
        #pragma unroll
        for (int d = 0; d < 64; d++) o[d] *= corr;
        #pragma unroll
        for (int j = 0; j < 32; j++) {
            float p = __expf(s[j] - m);
            l += p;
            #pragma unroll
            for (int d4 = 0; d4 < 16; d4++) {
                float4 vv = *(const float4*)&Vs[j][d4 * 4];
                o[4*d4+0] += p * vv.x; o[4*d4+1] += p * vv.y;
                o[4*d4+2] += p * vv.z; o[4*d4+3] += p * vv.w;
            }
        }
    }

    float inv = 1.0f / l;
    float4* op = (float4*)(out + ((size_t)(b * TSEQ + qi)) * DMODEL + h * HEADDIM);
    #pragma unroll
    for (int i = 0; i < 16; i++) {
        float4 r4;
        r4.x = o[4*i+0] * inv; r4.y = o[4*i+1] * inv;
        r4.z = o[4*i+2] * inv; r4.w = o[4*i+3] * inv;
        op[i] = r4;
    }
}

// -------------------- launch --------------------
extern "C" void kernel_launch(void* const* d_in, const int* in_sizes, int n_in,
                              void* d_out, int out_size)
{
    const float* x        = (const float*)d_in[0];
    const float* in_w     = (const float*)d_in[1];
    const float* in_b     = (const float*)d_in[2];
    const float* out_w    = (const float*)d_in[3];
    const float* out_b    = (const float*)d_in[4];
    const float* f1_w     = (const float*)d_in[5];
    const float* f1_b     = (const float*)d_in[6];
    const float* f2_w     = (const float*)d_in[7];
    const float* f2_b     = (const float*)d_in[8];
    const float* ln1_w    = (const float*)d_in[9];
    const float* ln1_b    = (const float*)d_in[10];
    const float* ln2_w    = (const float*)d_in[11];
    const float* ln2_b    = (const float*)d_in[12];
    const float* final_w  = (const float*)d_in[13];
    const float* final_b  = (const float*)d_in[14];

    float *x_, *xn_, *qkv_, *att_, *h_;
    cudaGetSymbolAddress((void**)&x_,   g_x);
    cudaGetSymbolAddress((void**)&xn_,  g_xn);
    cudaGetSymbolAddress((void**)&qkv_, g_qkv);
    cudaGetSymbolAddress((void**)&att_, g_att);
    cudaGetSymbolAddress((void**)&h_,   g_h);

    // residual stream init
    {
        int n4 = ROWS * DMODEL / 4;
        copy_kernel<<<(n4 + 255) / 256, 256>>>((const float4*)x, (float4*)x_, n4);
    }

    dim3 blk256(256);
    for (int i = 0; i < NLAYER; i++) {
        const float* iw  = in_w  + (size_t)i * QKVDIM * DMODEL;
        const float* ib  = in_b  + (size_t)i * QKVDIM;
        const float* ow  = out_w + (size_t)i * DMODEL * DMODEL;
        const float* ob  = out_b + (size_t)i * DMODEL;
        const float* w1  = f1_w  + (size_t)i * FFDIM * DMODEL;
        const float* b1  = f1_b  + (size_t)i * FFDIM;
        const float* w2  = f2_w  + (size_t)i * DMODEL * FFDIM;
        const float* b2  = f2_b  + (size_t)i * DMODEL;

        // LN1
        ln_kernel<<<ROWS, blk256>>>(x_, ln1_w + i * DMODEL, ln1_b + i * DMODEL, xn_);
        // QKV projection: (4096,3072,1024)
        gemm_kernel<0><<<dim3(QKVDIM / 128, ROWS / 128), blk256>>>(
            xn_, iw, ib, nullptr, qkv_, ROWS, QKVDIM, DMODEL);
        // attention
        attn_kernel<<<dim3(TSEQ / 128, NHEAD, BATCH), 128>>>(qkv_, att_);
        // out projection + residual: (4096,1024,1024)
        gemm_kernel<2><<<dim3(DMODEL / 128, ROWS / 128), blk256>>>(
            att_, ow, ob, x_, x_, ROWS, DMODEL, DMODEL);
        // LN2
        ln_kernel<<<ROWS, blk256>>>(x_, ln2_w + i * DMODEL, ln2_b + i * DMODEL, xn_);
        // FFN1 + GELU: (4096,4096,1024)
        gemm_kernel<1><<<dim3(FFDIM / 128, ROWS / 128), blk256>>>(
            xn_, w1, b1, nullptr, h_, ROWS, FFDIM, DMODEL);
        // FFN2 + residual: (4096,1024,4096)
        gemm_kernel<2><<<dim3(DMODEL / 128, ROWS / 128), blk256>>>(
            h_, w2, b2, x_, x_, ROWS, DMODEL, FFDIM);
    }
    // final LN -> output
    ln_kernel<<<ROWS, blk256>>>(x_, final_w, final_b, (float*)d_out);
}

// round 3
// speedup vs baseline: 1.2652x; 1.2652x over previous
#include <cuda_runtime.h>
#include <math.h>
#include <stdint.h>

// Problem constants
#define TSEQ    2048
#define BATCH   2
#define DMODEL  1024
#define NHEAD   16
#define HEADDIM 64
#define FFDIM   4096
#define NLAYER  4
#define ROWS    (BATCH * TSEQ)          // 4096
#define QKVDIM  (3 * DMODEL)            // 3072

// -------------------- scratch (allocation-free) --------------------
__device__ float g_x  [ROWS * DMODEL];   // residual stream
__device__ float g_xn [ROWS * DMODEL];   // layernorm output
__device__ float g_qkv[ROWS * QKVDIM];   // qkv projection
__device__ float g_att[ROWS * DMODEL];   // attention output
__device__ float g_h  [ROWS * FFDIM];    // ffn hidden

// -------------------- helpers --------------------
__device__ __forceinline__ void cp_async16(uint32_t smem, const void* g) {
    asm volatile("cp.async.cg.shared.global [%0], [%1], 16;\n" :: "r"(smem), "l"(g));
}
__device__ __forceinline__ void cp_commit() {
    asm volatile("cp.async.commit_group;\n" ::: "memory");
}
__device__ __forceinline__ void cp_wait0() {
    asm volatile("cp.async.wait_group 0;\n" ::: "memory");
}
__device__ __forceinline__ uint32_t f2tf32(float v) {
    uint32_t r;
    asm("cvt.rna.tf32.f32 %0, %1;" : "=r"(r) : "f"(v));
    return r;
}
__device__ __forceinline__ void mma_tf32(float* d, const uint32_t* a, const uint32_t* b) {
    asm volatile(
        "mma.sync.aligned.m16n8k8.row.col.f32.tf32.tf32.f32 "
        "{%0,%1,%2,%3}, {%4,%5,%6,%7}, {%8,%9}, {%0,%1,%2,%3};\n"
        : "+f"(d[0]), "+f"(d[1]), "+f"(d[2]), "+f"(d[3])
        : "r"(a[0]), "r"(a[1]), "r"(a[2]), "r"(a[3]),
          "r"(b[0]), "r"(b[1]));
}

// -------------------- copy --------------------
__global__ void copy_kernel(const float4* __restrict__ in, float4* __restrict__ out, int n4) {
    int i = blockIdx.x * blockDim.x + threadIdx.x;
    if (i < n4) out[i] = in[i];
}

// -------------------- layernorm --------------------
__global__ void __launch_bounds__(256) ln_kernel(
    const float* __restrict__ in, const float* __restrict__ w,
    const float* __restrict__ b, float* __restrict__ out)
{
    int row = blockIdx.x;
    int tid = threadIdx.x;
    const float4* ip = (const float4*)(in + (size_t)row * DMODEL);
    float4 v = ip[tid];
    float s  = v.x + v.y + v.z + v.w;
    float sq = v.x * v.x + v.y * v.y + v.z * v.z + v.w * v.w;

    #pragma unroll
    for (int o = 16; o > 0; o >>= 1) {
        s  += __shfl_xor_sync(0xffffffffu, s,  o);
        sq += __shfl_xor_sync(0xffffffffu, sq, o);
    }
    __shared__ float reds[8], redq[8];
    int lane = tid & 31, wid = tid >> 5;
    if (lane == 0) { reds[wid] = s; redq[wid] = sq; }
    __syncthreads();
    float ts = 0.f, tq = 0.f;
    #pragma unroll
    for (int i = 0; i < 8; i++) { ts += reds[i]; tq += redq[i]; }
    float mean = ts * (1.0f / DMODEL);
    float var  = tq * (1.0f / DMODEL) - mean * mean;
    float rstd = rsqrtf(var + 1e-5f);

    float4 wv = ((const float4*)w)[tid];
    float4 bv = ((const float4*)b)[tid];
    float4 r;
    r.x = (v.x - mean) * rstd * wv.x + bv.x;
    r.y = (v.y - mean) * rstd * wv.y + bv.y;
    r.z = (v.z - mean) * rstd * wv.z + bv.z;
    r.w = (v.w - mean) * rstd * wv.w + bv.w;
    ((float4*)(out + (size_t)row * DMODEL))[tid] = r;
}

// -------------------- 3xTF32 tensor-core GEMM --------------------
// C[M,N] = A[M,K] @ W[N,K]^T + bias, EPI: 0=bias, 1=bias+GELU, 2=bias+residual
// Block tile 256(M) x 128(N), BK=32, 256 threads = 8 warps (4M x 2N),
// warp tile 64x64 via m16n8k8 tf32 mma; each operand split hi/lo (3 mma passes)
// for fp32-class accuracy. Smem pitch 36 -> conflict-free fragment LDS.
#define GP 36
#define ASTG (256 * GP)
#define BSTG (128 * GP)
#define GEMM_SMEM ((2 * ASTG + 2 * BSTG) * 4)

template <int EPI>
__global__ void __launch_bounds__(256, 1) gemm_tf32(
    const float* __restrict__ A, const float* __restrict__ W,
    const float* __restrict__ bias, const float* __restrict__ res,
    float* __restrict__ C, int M, int N, int K)
{
    extern __shared__ float smem[];
    float* As = smem;                 // [2][256][GP]
    float* Bs = smem + 2 * ASTG;      // [2][128][GP]
    uint32_t sAb = (uint32_t)__cvta_generic_to_shared(As);
    uint32_t sBb = (uint32_t)__cvta_generic_to_shared(Bs);

    int tid  = threadIdx.x;
    int lane = tid & 31;
    int wid  = tid >> 5;
    int warpM = (wid >> 1) * 64;      // 0,64,128,192
    int warpN = (wid & 1) * 64;       // 0,64
    int m0 = blockIdx.y * 256;
    int n0 = blockIdx.x * 128;

    int gr = lane >> 2;               // groupID 0..7
    int gc = lane & 3;                // threadInGroup 0..3

    float acc[4][8][4];
    #pragma unroll
    for (int i = 0; i < 4; i++)
        #pragma unroll
        for (int j = 0; j < 8; j++)
            #pragma unroll
            for (int c = 0; c < 4; c++) acc[i][j][c] = 0.f;

    int KT = K >> 5;

    auto load_tiles = [&](int stage, int k0) {
        uint32_t sa = sAb + (uint32_t)stage * ASTG * 4;
        uint32_t sb = sBb + (uint32_t)stage * BSTG * 4;
        #pragma unroll
        for (int i = 0; i < 8; i++) {
            int f   = tid + i * 256;
            int row = f >> 3;
            int kq  = (f & 7) << 2;
            cp_async16(sa + (uint32_t)(row * GP + kq) * 4,
                       A + (size_t)(m0 + row) * K + k0 + kq);
        }
        #pragma unroll
        for (int i = 0; i < 4; i++) {
            int f   = tid + i * 256;
            int row = f >> 3;
            int kq  = (f & 7) << 2;
            cp_async16(sb + (uint32_t)(row * GP + kq) * 4,
                       W + (size_t)(n0 + row) * K + k0 + kq);
        }
        cp_commit();
    };

    load_tiles(0, 0);

    for (int kt = 0; kt < KT; kt++) {
        cp_wait0();
        __syncthreads();
        if (kt + 1 < KT) load_tiles((kt + 1) & 1, (kt + 1) << 5);

        const float* as = As + (kt & 1) * ASTG;
        const float* bs = Bs + (kt & 1) * BSTG;

        #pragma unroll
        for (int ks = 0; ks < 4; ks++) {
            int kb = ks * 8;
            // B fragments: split hi/lo
            uint32_t bh[8][2], bl[8][2];
            #pragma unroll
            for (int nt = 0; nt < 8; nt++) {
                int c = warpN + nt * 8 + gr;
                #pragma unroll
                for (int i = 0; i < 2; i++) {
                    float v = bs[c * GP + kb + gc + i * 4];
                    uint32_t h = f2tf32(v);
                    bh[nt][i] = h;
                    bl[nt][i] = f2tf32(v - __uint_as_float(h));
                }
            }
            #pragma unroll
            for (int mt = 0; mt < 4; mt++) {
                int r = warpM + mt * 16 + gr;
                float av[4];
                av[0] = as[r * GP + kb + gc];
                av[1] = as[(r + 8) * GP + kb + gc];
                av[2] = as[r * GP + kb + gc + 4];
                av[3] = as[(r + 8) * GP + kb + gc + 4];
                uint32_t ah[4], al[4];
                #pragma unroll
                for (int i = 0; i < 4; i++) {
                    uint32_t h = f2tf32(av[i]);
                    ah[i] = h;
                    al[i] = f2tf32(av[i] - __uint_as_float(h));
                }
                #pragma unroll
                for (int nt = 0; nt < 8; nt++) {
                    mma_tf32(acc[mt][nt], al, bh[nt]);   // lo*hi
                    mma_tf32(acc[mt][nt], ah, bl[nt]);   // hi*lo
                    mma_tf32(acc[mt][nt], ah, bh[nt]);   // hi*hi
                }
            }
        }
        __syncthreads();
    }

    // ---- epilogue ----
    #pragma unroll
    for (int mt = 0; mt < 4; mt++) {
        int r0 = m0 + warpM + mt * 16 + gr;
        #pragma unroll
        for (int nt = 0; nt < 8; nt++) {
            int col = n0 + warpN + nt * 8 + 2 * gc;
            float b0 = bias[col], b1 = bias[col + 1];
            #pragma unroll
            for (int half = 0; half < 2; half++) {
                int row = r0 + half * 8;
                float v0 = acc[mt][nt][2 * half + 0] + b0;
                float v1 = acc[mt][nt][2 * half + 1] + b1;
                if (EPI == 1) {
                    v0 = 0.5f * v0 * (1.0f + erff(v0 * 0.70710678118654752f));
                    v1 = 0.5f * v1 * (1.0f + erff(v1 * 0.70710678118654752f));
                } else if (EPI == 2) {
                    const float2 rv = *(const float2*)(res + (size_t)row * N + col);
                    v0 += rv.x; v1 += rv.y;
                }
                float2 o2; o2.x = v0; o2.y = v1;
                *(float2*)(C + (size_t)row * N + col) = o2;
            }
        }
    }
}

// -------------------- flash attention (fp32, causal + ALiBi) --------------------
__global__ void __launch_bounds__(128) attn_kernel(
    const float* __restrict__ qkv, float* __restrict__ out)
{
    int b    = blockIdx.z;
    int h    = blockIdx.y;
    int qblk = blockIdx.x;
    int qi   = qblk * 128 + threadIdx.x;

    __shared__ float Ks[32][64];
    __shared__ float Vs[32][64];

    float q[64];
    {
        const float4* qp = (const float4*)(qkv + ((size_t)(b * TSEQ + qi)) * QKVDIM + h * HEADDIM);
        #pragma unroll
        for (int i = 0; i < 16; i++) {
            float4 t4 = qp[i];
            q[4*i+0] = t4.x; q[4*i+1] = t4.y; q[4*i+2] = t4.z; q[4*i+3] = t4.w;
        }
    }

    float o[64];
    #pragma unroll
    for (int d = 0; d < 64; d++) o[d] = 0.f;
    float m = -INFINITY, l = 0.f;
    float slope = exp2f(-0.5f * (float)(h + 1));

    int ntiles = qblk * 4 + 4;

    for (int t = 0; t < ntiles; t++) {
        int kbase = t * 32;
        __syncthreads();
        #pragma unroll
        for (int i = 0; i < 4; i++) {
            int f = threadIdx.x + i * 128;
            int r = f >> 4;
            int c = (f & 15) * 4;
            const float* kp = qkv + ((size_t)(b * TSEQ + kbase + r)) * QKVDIM + DMODEL + h * HEADDIM + c;
            *(float4*)&Ks[r][c] = *(const float4*)kp;
            *(float4*)&Vs[r][c] = *(const float4*)(kp + DMODEL);
        }
        __syncthreads();

        float s[32];
        #pragma unroll
        for (int j = 0; j < 32; j++) {
            float acc2 = 0.f;
            #pragma unroll
            for (int d4 = 0; d4 < 16; d4++) {
                float4 kv = *(const float4*)&Ks[j][d4 * 4];
                acc2 += q[4*d4+0] * kv.x + q[4*d4+1] * kv.y
                      + q[4*d4+2] * kv.z + q[4*d4+3] * kv.w;
            }
            int kpos = kbase + j;
            s[j] = (kpos <= qi) ? (0.125f * acc2 + slope * (float)(kpos - qi)) : -INFINITY;
        }

        float tm = m;
        #pragma unroll
        for (int j = 0; j < 32; j++) tm = fmaxf(tm, s[j]);
        float corr = __expf(m - tm);
        m = tm;
        l *= corr;
        #pragma unroll
        for (int d = 0; d < 64; d++) o[d] *= corr;
        #pragma unroll
        for (int j = 0; j < 32; j++) {
            float p = __expf(s[j] - m);
            l += p;
            #pragma unroll
            for (int d4 = 0; d4 < 16; d4++) {
                float4 vv = *(const float4*)&Vs[j][d4 * 4];
                o[4*d4+0] += p * vv.x; o[4*d4+1] += p * vv.y;
                o[4*d4+2] += p * vv.z; o[4*d4+3] += p * vv.w;
            }
        }
    }

    float inv = 1.0f / l;
    float4* op = (float4*)(out + ((size_t)(b * TSEQ + qi)) * DMODEL + h * HEADDIM);
    #pragma unroll
    for (int i = 0; i < 16; i++) {
        float4 r4;
        r4.x = o[4*i+0] * inv; r4.y = o[4*i+1] * inv;
        r4.z = o[4*i+2] * inv; r4.w = o[4*i+3] * inv;
        op[i] = r4;
    }
}

// -------------------- launch --------------------
extern "C" void kernel_launch(void* const* d_in, const int* in_sizes, int n_in,
                              void* d_out, int out_size)
{
    const float* x        = (const float*)d_in[0];
    const float* in_w     = (const float*)d_in[1];
    const float* in_b     = (const float*)d_in[2];
    const float* out_w    = (const float*)d_in[3];
    const float* out_b    = (const float*)d_in[4];
    const float* f1_w     = (const float*)d_in[5];
    const float* f1_b     = (const float*)d_in[6];
    const float* f2_w     = (const float*)d_in[7];
    const float* f2_b     = (const float*)d_in[8];
    const float* ln1_w    = (const float*)d_in[9];
    const float* ln1_b    = (const float*)d_in[10];
    const float* ln2_w    = (const float*)d_in[11];
    const float* ln2_b    = (const float*)d_in[12];
    const float* final_w  = (const float*)d_in[13];
    const float* final_b  = (const float*)d_in[14];

    float *x_, *xn_, *qkv_, *att_, *h_;
    cudaGetSymbolAddress((void**)&x_,   g_x);
    cudaGetSymbolAddress((void**)&xn_,  g_xn);
    cudaGetSymbolAddress((void**)&qkv_, g_qkv);
    cudaGetSymbolAddress((void**)&att_, g_att);
    cudaGetSymbolAddress((void**)&h_,   g_h);

    cudaFuncSetAttribute(gemm_tf32<0>, cudaFuncAttributeMaxDynamicSharedMemorySize, GEMM_SMEM);
    cudaFuncSetAttribute(gemm_tf32<1>, cudaFuncAttributeMaxDynamicSharedMemorySize, GEMM_SMEM);
    cudaFuncSetAttribute(gemm_tf32<2>, cudaFuncAttributeMaxDynamicSharedMemorySize, GEMM_SMEM);

    {
        int n4 = ROWS * DMODEL / 4;
        copy_kernel<<<(n4 + 255) / 256, 256>>>((const float4*)x, (float4*)x_, n4);
    }

    dim3 blk256(256);
    for (int i = 0; i < NLAYER; i++) {
        const float* iw  = in_w  + (size_t)i * QKVDIM * DMODEL;
        const float* ib  = in_b  + (size_t)i * QKVDIM;
        const float* ow  = out_w + (size_t)i * DMODEL * DMODEL;
        const float* ob  = out_b + (size_t)i * DMODEL;
        const float* w1  = f1_w  + (size_t)i * FFDIM * DMODEL;
        const float* b1  = f1_b  + (size_t)i * FFDIM;
        const float* w2  = f2_w  + (size_t)i * DMODEL * FFDIM;
        const float* b2  = f2_b  + (size_t)i * DMODEL;

        ln_kernel<<<ROWS, blk256>>>(x_, ln1_w + i * DMODEL, ln1_b + i * DMODEL, xn_);
        gemm_tf32<0><<<dim3(QKVDIM / 128, ROWS / 256), blk256, GEMM_SMEM>>>(
            xn_, iw, ib, nullptr, qkv_, ROWS, QKVDIM, DMODEL);
        attn_kernel<<<dim3(TSEQ / 128, NHEAD, BATCH), 128>>>(qkv_, att_);
        gemm_tf32<2><<<dim3(DMODEL / 128, ROWS / 256), blk256, GEMM_SMEM>>>(
            att_, ow, ob, x_, x_, ROWS, DMODEL, DMODEL);
        ln_kernel<<<ROWS, blk256>>>(x_, ln2_w + i * DMODEL, ln2_b + i * DMODEL, xn_);
        gemm_tf32<1><<<dim3(FFDIM / 128, ROWS / 256), blk256, GEMM_SMEM>>>(
            xn_, w1, b1, nullptr, h_, ROWS, FFDIM, DMODEL);
        gemm_tf32<2><<<dim3(DMODEL / 128, ROWS / 256), blk256, GEMM_SMEM>>>(
            h_, w2, b2, x_, x_, ROWS, DMODEL, FFDIM);
    }
    ln_kernel<<<ROWS, blk256>>>(x_, final_w, final_b, (float*)d_out);
}